// round 1
// baseline (speedup 1.0000x reference)
#include <cuda_runtime.h>

#define NP 500000
#define NB 20000
#define NC 5000
#define NS 2000
#define NTOT 527000
#define NE 500000
#define H 64
#define FIN 384

// ---------------- scratch (device globals; no runtime allocation) ----------
__device__ float g_x[(size_t)NTOT * H];    // layer-1 input features
__device__ float g_h[(size_t)NTOT * H];    // layer-1 output features
__device__ float g_agg[(size_t)NTOT * H];  // neighbor-mean accumulator
__device__ float g_inv[NTOT];              // 1 / max(deg, 1)

// ---------------- utility kernels ------------------------------------------
__global__ void __launch_bounds__(256) zero_buffers(int zero_cnt) {
    int i = blockIdx.x * 256 + threadIdx.x;
    if (i < NTOT * H / 4)
        reinterpret_cast<float4*>(g_agg)[i] = make_float4(0.f, 0.f, 0.f, 0.f);
    if (zero_cnt && i < NTOT) g_inv[i] = 0.f;
}

__global__ void __launch_bounds__(256) copy_emb(const float* __restrict__ eb,
                                                const float* __restrict__ ec,
                                                const float* __restrict__ es) {
    int i = blockIdx.x * 256 + threadIdx.x;  // float4 index
    const int tot = (NB + NC + NS) * H / 4;
    if (i >= tot) return;
    const int nb4 = NB * H / 4, nc4 = NC * H / 4;
    float4 v;
    if (i < nb4) v = reinterpret_cast<const float4*>(eb)[i];
    else if (i < nb4 + nc4) v = reinterpret_cast<const float4*>(ec)[i - nb4];
    else v = reinterpret_cast<const float4*>(es)[i - nb4 - nc4];
    reinterpret_cast<float4*>(g_x)[(size_t)NP * H / 4 + i] = v;
}

__global__ void __launch_bounds__(256) count_edges(
    const int* __restrict__ pb_src, const int* __restrict__ pb_dst,
    const int* __restrict__ pc_src, const int* __restrict__ pc_dst,
    const int* __restrict__ ps_src, const int* __restrict__ ps_dst) {
    int e = blockIdx.x * 256 + threadIdx.x;
    if (e >= 3 * NE) return;
    int t = e / NE, i = e - t * NE;
    const int* sp; const int* dp; int off;
    if (t == 0)      { sp = pb_src; dp = pb_dst; off = NP; }
    else if (t == 1) { sp = pc_src; dp = pc_dst; off = NP + NB; }
    else             { sp = ps_src; dp = ps_dst; off = NP + NB + NC; }
    int p = __ldg(sp + i);
    int o = __ldg(dp + i) + off;
    atomicAdd(&g_inv[p], 1.f);  // reverse edge lands on product
    atomicAdd(&g_inv[o], 1.f);  // forward edge lands on brand/cat/shop
}

__global__ void __launch_bounds__(256) invert_counts() {
    int i = blockIdx.x * 256 + threadIdx.x;
    if (i < NTOT) g_inv[i] = 1.f / fmaxf(g_inv[i], 1.f);
}

// ---------------- edge scatter: one warp per undirected edge pair ----------
// Folds 1/deg(dst) into the scatter so g_agg ends up holding the MEAN.
__global__ void __launch_bounds__(256) edge_scatter(
    int use_h,
    const int* __restrict__ pb_src, const int* __restrict__ pb_dst,
    const int* __restrict__ pc_src, const int* __restrict__ pc_dst,
    const int* __restrict__ ps_src, const int* __restrict__ ps_dst) {
    int gw = (blockIdx.x * 256 + threadIdx.x) >> 5;
    if (gw >= 3 * NE) return;
    int lane = threadIdx.x & 31;
    int t = gw / NE, i = gw - t * NE;
    const int* sp; const int* dp; int off;
    if (t == 0)      { sp = pb_src; dp = pb_dst; off = NP; }
    else if (t == 1) { sp = pc_src; dp = pc_dst; off = NP + NB; }
    else             { sp = ps_src; dp = ps_dst; off = NP + NB + NC; }
    int p = __ldg(sp + i);
    int o = __ldg(dp + i) + off;
    const float* x = use_h ? g_h : g_x;
    int s, d, f;
    if (lane < 16) { s = p; d = o; f = lane * 4; }          // forward: x[p] -> agg[o]
    else           { s = o; d = p; f = (lane - 16) * 4; }   // reverse: x[o] -> agg[p]
    float inv = g_inv[d];
    float4 v = *reinterpret_cast<const float4*>(x + (size_t)s * H + f);
    float* dst = g_agg + (size_t)d * H + f;
    asm volatile("red.global.add.v4.f32 [%0], {%1,%2,%3,%4};"
                 :: "l"(dst), "f"(v.x * inv), "f"(v.y * inv),
                    "f"(v.z * inv), "f"(v.w * inv)
                 : "memory");
}

// ---------------- projection GEMM: relu(x_product @ W_proj^T + b) ----------
// C[NP,64] = A[NP,384] * W[64,384]^T. Block: 256 rows x 64 cols, 8x8/thread.
__global__ void __launch_bounds__(256) proj_kernel(const float* __restrict__ A,
                                                   const float* __restrict__ W,
                                                   const float* __restrict__ bias) {
    constexpr int KT = 32;
    __shared__ __align__(16) float As[KT][256];
    __shared__ __align__(16) float Bs[KT][64];
    const int tid = threadIdx.x;
    const int m0 = blockIdx.x * 256;
    const int lr = tid / 8, lc = tid % 8;      // A loader coords
    const int tx = tid % 8, ty = tid / 8;      // compute coords

    float acc[8][8];
#pragma unroll
    for (int r = 0; r < 8; r++)
#pragma unroll
        for (int c = 0; c < 8; c++) acc[r][c] = 0.f;

    for (int kb = 0; kb < FIN; kb += KT) {
#pragma unroll
        for (int q = 0; q < 8; q++) {
            int row = m0 + lr + 32 * q;
            if (row > NP - 1) row = NP - 1;
            float4 v = *reinterpret_cast<const float4*>(A + (size_t)row * FIN + kb + lc * 4);
            int kl = lc * 4, ml = lr + 32 * q;
            As[kl + 0][ml] = v.x; As[kl + 1][ml] = v.y;
            As[kl + 2][ml] = v.z; As[kl + 3][ml] = v.w;
        }
        for (int idx = tid; idx < KT * 64; idx += 256) {
            int j = idx % 64, kk = idx / 64;   // conflict-free STS; W is L1-hot
            Bs[kk][j] = W[(size_t)j * FIN + kb + kk];
        }
        __syncthreads();
#pragma unroll
        for (int k = 0; k < KT; k++) {
            float4 a0 = *reinterpret_cast<const float4*>(&As[k][ty * 8]);
            float4 a1 = *reinterpret_cast<const float4*>(&As[k][ty * 8 + 4]);
            float4 b0 = *reinterpret_cast<const float4*>(&Bs[k][tx * 8]);
            float4 b1 = *reinterpret_cast<const float4*>(&Bs[k][tx * 8 + 4]);
            float av[8] = {a0.x, a0.y, a0.z, a0.w, a1.x, a1.y, a1.z, a1.w};
            float bv[8] = {b0.x, b0.y, b0.z, b0.w, b1.x, b1.y, b1.z, b1.w};
#pragma unroll
            for (int r = 0; r < 8; r++)
#pragma unroll
                for (int c = 0; c < 8; c++)
                    acc[r][c] = fmaf(av[r], bv[c], acc[r][c]);
        }
        __syncthreads();
    }
#pragma unroll
    for (int rr = 0; rr < 8; rr++) {
        int row = m0 + ty * 8 + rr;
        if (row >= NP) continue;
        float4 o0, o1;
        o0.x = fmaxf(acc[rr][0] + bias[tx * 8 + 0], 0.f);
        o0.y = fmaxf(acc[rr][1] + bias[tx * 8 + 1], 0.f);
        o0.z = fmaxf(acc[rr][2] + bias[tx * 8 + 2], 0.f);
        o0.w = fmaxf(acc[rr][3] + bias[tx * 8 + 3], 0.f);
        o1.x = fmaxf(acc[rr][4] + bias[tx * 8 + 4], 0.f);
        o1.y = fmaxf(acc[rr][5] + bias[tx * 8 + 5], 0.f);
        o1.z = fmaxf(acc[rr][6] + bias[tx * 8 + 6], 0.f);
        o1.w = fmaxf(acc[rr][7] + bias[tx * 8 + 7], 0.f);
        *reinterpret_cast<float4*>(g_x + (size_t)row * H + tx * 8) = o0;
        *reinterpret_cast<float4*>(g_x + (size_t)row * H + tx * 8 + 4) = o1;
    }
}

// ---------------- SAGE finalize: C = x @ Wr^T + mean @ Wl^T + b ------------
// Virtual K=128 GEMM: k<64 -> (xsrc, Wr); k>=64 -> (g_agg, Wl).
template <int MBLK, int NOUT, int KT, bool RELU, bool USEH>
__global__ void __launch_bounds__(256) finalize_gemm(const float* __restrict__ Wr,
                                                     const float* __restrict__ Wl,
                                                     const float* __restrict__ bias,
                                                     float* __restrict__ outp) {
    __shared__ __align__(16) float As[KT][MBLK];
    __shared__ __align__(16) float Bs[KT][NOUT];
    const int tid = threadIdx.x;
    const int m0 = blockIdx.x * MBLK;
    constexpr int LK = KT / 4;
    constexpr int RSPAN = 256 / LK;
    const int lr = tid / LK, lc = tid % LK;
    constexpr int NTX = NOUT / 8;
    const int tx = tid % NTX, ty = tid / NTX;
    const float* xsrc = USEH ? g_h : g_x;
    float* out = (NOUT == H) ? g_h : outp;

    float acc[8][8];
#pragma unroll
    for (int r = 0; r < 8; r++)
#pragma unroll
        for (int c = 0; c < 8; c++) acc[r][c] = 0.f;

    for (int kb = 0; kb < 2 * H; kb += KT) {
        const float* src = (kb < H) ? xsrc : g_agg;
        const float* W = (kb < H) ? Wr : Wl;
        const int kcol = kb & (H - 1);
#pragma unroll
        for (int q = 0; q < MBLK / RSPAN; q++) {
            int row = m0 + lr + RSPAN * q;
            if (row > NTOT - 1) row = NTOT - 1;
            float4 v = *reinterpret_cast<const float4*>(src + (size_t)row * H + kcol + lc * 4);
            int kl = lc * 4, ml = lr + RSPAN * q;
            As[kl + 0][ml] = v.x; As[kl + 1][ml] = v.y;
            As[kl + 2][ml] = v.z; As[kl + 3][ml] = v.w;
        }
        for (int idx = tid; idx < KT * NOUT; idx += 256) {
            int j = idx % NOUT, kk = idx / NOUT;
            Bs[kk][j] = W[(size_t)j * H + kcol + kk];
        }
        __syncthreads();
#pragma unroll
        for (int k = 0; k < KT; k++) {
            float4 a0 = *reinterpret_cast<const float4*>(&As[k][ty * 8]);
            float4 a1 = *reinterpret_cast<const float4*>(&As[k][ty * 8 + 4]);
            float4 b0 = *reinterpret_cast<const float4*>(&Bs[k][tx * 8]);
            float4 b1 = *reinterpret_cast<const float4*>(&Bs[k][tx * 8 + 4]);
            float av[8] = {a0.x, a0.y, a0.z, a0.w, a1.x, a1.y, a1.z, a1.w};
            float bv[8] = {b0.x, b0.y, b0.z, b0.w, b1.x, b1.y, b1.z, b1.w};
#pragma unroll
            for (int r = 0; r < 8; r++)
#pragma unroll
                for (int c = 0; c < 8; c++)
                    acc[r][c] = fmaf(av[r], bv[c], acc[r][c]);
        }
        __syncthreads();
    }
#pragma unroll
    for (int rr = 0; rr < 8; rr++) {
        int row = m0 + ty * 8 + rr;
        if (row >= NTOT) continue;
        float4 o0, o1;
        float* op = out + (size_t)row * NOUT + tx * 8;
#pragma unroll
        for (int c = 0; c < 4; c++) {
            float v = acc[rr][c] + bias[tx * 8 + c];
            (&o0.x)[c] = RELU ? fmaxf(v, 0.f) : v;
        }
#pragma unroll
        for (int c = 0; c < 4; c++) {
            float v = acc[rr][4 + c] + bias[tx * 8 + 4 + c];
            (&o1.x)[c] = RELU ? fmaxf(v, 0.f) : v;
        }
        *reinterpret_cast<float4*>(op) = o0;
        *reinterpret_cast<float4*>(op + 4) = o1;
    }
}

// ---------------- launch ----------------------------------------------------
extern "C" void kernel_launch(void* const* d_in, const int* in_sizes, int n_in,
                              void* d_out, int out_size) {
    const float* x_product = (const float*)d_in[0];
    const int* pb_src = (const int*)d_in[1];
    const int* pb_dst = (const int*)d_in[2];
    const int* pc_src = (const int*)d_in[3];
    const int* pc_dst = (const int*)d_in[4];
    const int* ps_src = (const int*)d_in[5];
    const int* ps_dst = (const int*)d_in[6];
    const float* W_proj = (const float*)d_in[7];
    const float* b_proj = (const float*)d_in[8];
    const float* emb_brand = (const float*)d_in[9];
    const float* emb_cat = (const float*)d_in[10];
    const float* emb_shop = (const float*)d_in[11];
    const float* W1_l = (const float*)d_in[12];
    const float* b1_l = (const float*)d_in[13];
    const float* W1_r = (const float*)d_in[14];
    const float* W2_l = (const float*)d_in[15];
    const float* b2_l = (const float*)d_in[16];
    const float* W2_r = (const float*)d_in[17];
    float* out = (float*)d_out;

    const int zeroBlocks = (NTOT * H / 4 + 255) / 256;
    const int edgeBlocks = (3 * NE + 7) / 8;  // 1 warp per edge pair

    // zero agg + degree counters
    zero_buffers<<<zeroBlocks, 256>>>(1);
    // assemble node features
    proj_kernel<<<(NP + 255) / 256, 256>>>(x_product, W_proj, b_proj);
    copy_emb<<<((NB + NC + NS) * H / 4 + 255) / 256, 256>>>(emb_brand, emb_cat, emb_shop);
    // degrees -> 1/deg (shared by both layers)
    count_edges<<<(3 * NE + 255) / 256, 256>>>(pb_src, pb_dst, pc_src, pc_dst, ps_src, ps_dst);
    invert_counts<<<(NTOT + 255) / 256, 256>>>();
    // layer 1
    edge_scatter<<<edgeBlocks, 256>>>(0, pb_src, pb_dst, pc_src, pc_dst, ps_src, ps_dst);
    finalize_gemm<256, 64, 32, true, false><<<(NTOT + 255) / 256, 256>>>(W1_r, W1_l, b1_l, out);
    // layer 2
    zero_buffers<<<zeroBlocks, 256>>>(0);
    edge_scatter<<<edgeBlocks, 256>>>(1, pb_src, pb_dst, pc_src, pc_dst, ps_src, ps_dst);
    finalize_gemm<512, 32, 16, false, true><<<(NTOT + 511) / 512, 256>>>(W2_r, W2_l, b2_l, out);
}

// round 2
// speedup vs baseline: 1.0481x; 1.0481x over previous
#include <cuda_runtime.h>

#define NP 500000
#define NB 20000
#define NC 5000
#define NS 2000
#define NTOT 527000
#define NE 500000
#define EDIR (3 * NE * 2)   // 3M directed edges
#define H 64
#define FIN 384

#define SCAN_SPAN 2048
#define NBLK_SCAN ((NTOT + SCAN_SPAN - 1) / SCAN_SPAN)   // 258

// ---------------- scratch (device globals; no runtime allocation) ----------
__device__ float g_x[(size_t)NTOT * H];    // layer-1 input features
__device__ float g_h[(size_t)NTOT * H];    // layer-1 output features
__device__ float g_agg[(size_t)NTOT * H];  // neighbor-mean (written fully, no zeroing)
__device__ int   g_deg[NTOT];
__device__ int   g_rowstart[NTOT];
__device__ int   g_cursor[NTOT];
__device__ int   g_scaninc[NTOT];
__device__ int   g_blocksum[512];
__device__ int   g_adj[EDIR];

// ---------------- CSR build -------------------------------------------------
__global__ void __launch_bounds__(256) zero_deg() {
    int i = blockIdx.x * 256 + threadIdx.x;
    if (i < NTOT) g_deg[i] = 0;
}

__global__ void __launch_bounds__(256) hist_edges(
    const int* __restrict__ pb_src, const int* __restrict__ pb_dst,
    const int* __restrict__ pc_src, const int* __restrict__ pc_dst,
    const int* __restrict__ ps_src, const int* __restrict__ ps_dst) {
    int e = blockIdx.x * 256 + threadIdx.x;
    if (e >= 3 * NE) return;
    int t = e / NE, i = e - t * NE;
    const int* sp; const int* dp; int off;
    if (t == 0)      { sp = pb_src; dp = pb_dst; off = NP; }
    else if (t == 1) { sp = pc_src; dp = pc_dst; off = NP + NB; }
    else             { sp = ps_src; dp = ps_dst; off = NP + NB + NC; }
    int p = __ldg(sp + i);
    int o = __ldg(dp + i) + off;
    atomicAdd(&g_deg[p], 1);
    atomicAdd(&g_deg[o], 1);
}

// block-local inclusive scan over 2048 ints, records block total
__global__ void __launch_bounds__(256) scanA() {
    __shared__ int wsum[8];
    __shared__ int wpre[8];
    int tid = threadIdx.x, lane = tid & 31, wid = tid >> 5;
    int base = blockIdx.x * SCAN_SPAN + tid * 8;
    int v[8], run = 0;
#pragma unroll
    for (int t = 0; t < 8; t++) {
        int idx = base + t;
        int d = (idx < NTOT) ? g_deg[idx] : 0;
        run += d;
        v[t] = run;
    }
    int tot = run;
#pragma unroll
    for (int off = 1; off < 32; off <<= 1) {
        int n = __shfl_up_sync(0xffffffffu, tot, off);
        if (lane >= off) tot += n;
    }
    int wexcl = tot - run;
    if (lane == 31) wsum[wid] = tot;
    __syncthreads();
    if (tid < 8) {
        int s = wsum[tid];
        int r = s;
#pragma unroll
        for (int off = 1; off < 8; off <<= 1) {
            int n = __shfl_up_sync(0xffu, r, off);
            if (tid >= off) r += n;
        }
        wpre[tid] = r - s;
        if (tid == 7) g_blocksum[blockIdx.x] = r;
    }
    __syncthreads();
    int bexcl = wexcl + wpre[wid];
#pragma unroll
    for (int t = 0; t < 8; t++) {
        int idx = base + t;
        if (idx < NTOT) g_scaninc[idx] = v[t] + bexcl;
    }
}

// exclusive scan of the 258 block sums (single block)
__global__ void __launch_bounds__(512) scanB() {
    __shared__ int s[NBLK_SCAN];
    int tid = threadIdx.x;
    if (tid < NBLK_SCAN) s[tid] = g_blocksum[tid];
    __syncthreads();
    if (tid == 0) {
        int run = 0;
        for (int i = 0; i < NBLK_SCAN; i++) { int t = s[i]; s[i] = run; run += t; }
    }
    __syncthreads();
    if (tid < NBLK_SCAN) g_blocksum[tid] = s[tid];
}

__global__ void __launch_bounds__(256) scanC() {
    int i = blockIdx.x * 256 + threadIdx.x;
    if (i >= NTOT) return;
    int start = g_scaninc[i] + g_blocksum[i >> 11] - g_deg[i];
    g_rowstart[i] = start;
    g_cursor[i] = start;
}

__global__ void __launch_bounds__(256) fill_csr(
    const int* __restrict__ pb_src, const int* __restrict__ pb_dst,
    const int* __restrict__ pc_src, const int* __restrict__ pc_dst,
    const int* __restrict__ ps_src, const int* __restrict__ ps_dst) {
    int e = blockIdx.x * 256 + threadIdx.x;
    if (e >= 3 * NE) return;
    int t = e / NE, i = e - t * NE;
    const int* sp; const int* dp; int off;
    if (t == 0)      { sp = pb_src; dp = pb_dst; off = NP; }
    else if (t == 1) { sp = pc_src; dp = pc_dst; off = NP + NB; }
    else             { sp = ps_src; dp = ps_dst; off = NP + NB + NC; }
    int p = __ldg(sp + i);
    int o = __ldg(dp + i) + off;
    int pos = atomicAdd(&g_cursor[o], 1);
    g_adj[pos] = p;                         // forward: p is o's neighbor
    int pos2 = atomicAdd(&g_cursor[p], 1);
    g_adj[pos2] = o;                        // reverse: o is p's neighbor
}

// ---------------- feature assembly ------------------------------------------
__global__ void __launch_bounds__(256) copy_emb(const float* __restrict__ eb,
                                                const float* __restrict__ ec,
                                                const float* __restrict__ es) {
    int i = blockIdx.x * 256 + threadIdx.x;  // float4 index
    const int tot = (NB + NC + NS) * H / 4;
    if (i >= tot) return;
    const int nb4 = NB * H / 4, nc4 = NC * H / 4;
    float4 v;
    if (i < nb4) v = reinterpret_cast<const float4*>(eb)[i];
    else if (i < nb4 + nc4) v = reinterpret_cast<const float4*>(ec)[i - nb4];
    else v = reinterpret_cast<const float4*>(es)[i - nb4 - nc4];
    reinterpret_cast<float4*>(g_x)[(size_t)NP * H / 4 + i] = v;
}

// ---------------- projection GEMM: relu(x_product @ W_proj^T + b) ----------
__global__ void __launch_bounds__(256) proj_kernel(const float* __restrict__ A,
                                                   const float* __restrict__ W,
                                                   const float* __restrict__ bias) {
    constexpr int KT = 32;
    __shared__ __align__(16) float As[KT][256];
    __shared__ __align__(16) float Bs[KT][64];
    const int tid = threadIdx.x;
    const int m0 = blockIdx.x * 256;
    const int lr = tid / 8, lc = tid % 8;
    const int tx = tid % 8, ty = tid / 8;

    float acc[8][8];
#pragma unroll
    for (int r = 0; r < 8; r++)
#pragma unroll
        for (int c = 0; c < 8; c++) acc[r][c] = 0.f;

    for (int kb = 0; kb < FIN; kb += KT) {
#pragma unroll
        for (int q = 0; q < 8; q++) {
            int row = m0 + lr + 32 * q;
            if (row > NP - 1) row = NP - 1;
            float4 v = *reinterpret_cast<const float4*>(A + (size_t)row * FIN + kb + lc * 4);
            int kl = lc * 4, ml = lr + 32 * q;
            As[kl + 0][ml] = v.x; As[kl + 1][ml] = v.y;
            As[kl + 2][ml] = v.z; As[kl + 3][ml] = v.w;
        }
        for (int idx = tid; idx < KT * 64; idx += 256) {
            int j = idx % 64, kk = idx / 64;
            Bs[kk][j] = W[(size_t)j * FIN + kb + kk];
        }
        __syncthreads();
#pragma unroll
        for (int k = 0; k < KT; k++) {
            float4 a0 = *reinterpret_cast<const float4*>(&As[k][ty * 8]);
            float4 a1 = *reinterpret_cast<const float4*>(&As[k][ty * 8 + 4]);
            float4 b0 = *reinterpret_cast<const float4*>(&Bs[k][tx * 8]);
            float4 b1 = *reinterpret_cast<const float4*>(&Bs[k][tx * 8 + 4]);
            float av[8] = {a0.x, a0.y, a0.z, a0.w, a1.x, a1.y, a1.z, a1.w};
            float bv[8] = {b0.x, b0.y, b0.z, b0.w, b1.x, b1.y, b1.z, b1.w};
#pragma unroll
            for (int r = 0; r < 8; r++)
#pragma unroll
                for (int c = 0; c < 8; c++)
                    acc[r][c] = fmaf(av[r], bv[c], acc[r][c]);
        }
        __syncthreads();
    }
#pragma unroll
    for (int rr = 0; rr < 8; rr++) {
        int row = m0 + ty * 8 + rr;
        if (row >= NP) continue;
        float4 o0, o1;
        o0.x = fmaxf(acc[rr][0] + bias[tx * 8 + 0], 0.f);
        o0.y = fmaxf(acc[rr][1] + bias[tx * 8 + 1], 0.f);
        o0.z = fmaxf(acc[rr][2] + bias[tx * 8 + 2], 0.f);
        o0.w = fmaxf(acc[rr][3] + bias[tx * 8 + 3], 0.f);
        o1.x = fmaxf(acc[rr][4] + bias[tx * 8 + 4], 0.f);
        o1.y = fmaxf(acc[rr][5] + bias[tx * 8 + 5], 0.f);
        o1.z = fmaxf(acc[rr][6] + bias[tx * 8 + 6], 0.f);
        o1.w = fmaxf(acc[rr][7] + bias[tx * 8 + 7], 0.f);
        *reinterpret_cast<float4*>(g_x + (size_t)row * H + tx * 8) = o0;
        *reinterpret_cast<float4*>(g_x + (size_t)row * H + tx * 8 + 4) = o1;
    }
}

// ---------------- CSR mean aggregation: one warp per node -------------------
__global__ void __launch_bounds__(256) aggregate(int use_h) {
    int gw = (blockIdx.x * 256 + threadIdx.x) >> 5;
    if (gw >= NTOT) return;
    int lane = threadIdx.x & 31;
    int start = g_rowstart[gw];
    int deg = g_deg[gw];
    const float* __restrict__ x = use_h ? g_h : g_x;
    int half = lane >> 4;
    int f = (lane & 15) * 4;
    float4 acc = make_float4(0.f, 0.f, 0.f, 0.f);
    for (int it = 0; 2 * it + half < deg; it++) {
        int s = __ldg(g_adj + start + 2 * it + half);
        float4 v = *reinterpret_cast<const float4*>(x + (size_t)s * H + f);
        acc.x += v.x; acc.y += v.y; acc.z += v.z; acc.w += v.w;
    }
    acc.x += __shfl_xor_sync(0xffffffffu, acc.x, 16);
    acc.y += __shfl_xor_sync(0xffffffffu, acc.y, 16);
    acc.z += __shfl_xor_sync(0xffffffffu, acc.z, 16);
    acc.w += __shfl_xor_sync(0xffffffffu, acc.w, 16);
    if (lane < 16) {
        float inv = 1.f / fmaxf((float)deg, 1.f);
        float4 o = make_float4(acc.x * inv, acc.y * inv, acc.z * inv, acc.w * inv);
        *reinterpret_cast<float4*>(g_agg + (size_t)gw * H + f) = o;
    }
}

// ---------------- SAGE finalize: C = x @ Wr^T + mean @ Wl^T + b ------------
template <int MBLK, int NOUT, int KT, bool RELU, bool USEH>
__global__ void __launch_bounds__(256) finalize_gemm(const float* __restrict__ Wr,
                                                     const float* __restrict__ Wl,
                                                     const float* __restrict__ bias,
                                                     float* __restrict__ outp) {
    __shared__ __align__(16) float As[KT][MBLK];
    __shared__ __align__(16) float Bs[KT][NOUT];
    const int tid = threadIdx.x;
    const int m0 = blockIdx.x * MBLK;
    constexpr int LK = KT / 4;
    constexpr int RSPAN = 256 / LK;
    const int lr = tid / LK, lc = tid % LK;
    constexpr int NTX = NOUT / 8;
    const int tx = tid % NTX, ty = tid / NTX;
    const float* xsrc = USEH ? g_h : g_x;
    float* out = (NOUT == H) ? g_h : outp;

    float acc[8][8];
#pragma unroll
    for (int r = 0; r < 8; r++)
#pragma unroll
        for (int c = 0; c < 8; c++) acc[r][c] = 0.f;

    for (int kb = 0; kb < 2 * H; kb += KT) {
        const float* src = (kb < H) ? xsrc : g_agg;
        const float* W = (kb < H) ? Wr : Wl;
        const int kcol = kb & (H - 1);
#pragma unroll
        for (int q = 0; q < MBLK / RSPAN; q++) {
            int row = m0 + lr + RSPAN * q;
            if (row > NTOT - 1) row = NTOT - 1;
            float4 v = *reinterpret_cast<const float4*>(src + (size_t)row * H + kcol + lc * 4);
            int kl = lc * 4, ml = lr + RSPAN * q;
            As[kl + 0][ml] = v.x; As[kl + 1][ml] = v.y;
            As[kl + 2][ml] = v.z; As[kl + 3][ml] = v.w;
        }
        for (int idx = tid; idx < KT * NOUT; idx += 256) {
            int j = idx % NOUT, kk = idx / NOUT;
            Bs[kk][j] = W[(size_t)j * H + kcol + kk];
        }
        __syncthreads();
#pragma unroll
        for (int k = 0; k < KT; k++) {
            float4 a0 = *reinterpret_cast<const float4*>(&As[k][ty * 8]);
            float4 a1 = *reinterpret_cast<const float4*>(&As[k][ty * 8 + 4]);
            float4 b0 = *reinterpret_cast<const float4*>(&Bs[k][tx * 8]);
            float4 b1 = *reinterpret_cast<const float4*>(&Bs[k][tx * 8 + 4]);
            float av[8] = {a0.x, a0.y, a0.z, a0.w, a1.x, a1.y, a1.z, a1.w};
            float bv[8] = {b0.x, b0.y, b0.z, b0.w, b1.x, b1.y, b1.z, b1.w};
#pragma unroll
            for (int r = 0; r < 8; r++)
#pragma unroll
                for (int c = 0; c < 8; c++)
                    acc[r][c] = fmaf(av[r], bv[c], acc[r][c]);
        }
        __syncthreads();
    }
#pragma unroll
    for (int rr = 0; rr < 8; rr++) {
        int row = m0 + ty * 8 + rr;
        if (row >= NTOT) continue;
        float4 o0, o1;
        float* op = out + (size_t)row * NOUT + tx * 8;
#pragma unroll
        for (int c = 0; c < 4; c++) {
            float v = acc[rr][c] + bias[tx * 8 + c];
            (&o0.x)[c] = RELU ? fmaxf(v, 0.f) : v;
        }
#pragma unroll
        for (int c = 0; c < 4; c++) {
            float v = acc[rr][4 + c] + bias[tx * 8 + 4 + c];
            (&o1.x)[c] = RELU ? fmaxf(v, 0.f) : v;
        }
        *reinterpret_cast<float4*>(op) = o0;
        *reinterpret_cast<float4*>(op + 4) = o1;
    }
}

// ---------------- launch ----------------------------------------------------
extern "C" void kernel_launch(void* const* d_in, const int* in_sizes, int n_in,
                              void* d_out, int out_size) {
    const float* x_product = (const float*)d_in[0];
    const int* pb_src = (const int*)d_in[1];
    const int* pb_dst = (const int*)d_in[2];
    const int* pc_src = (const int*)d_in[3];
    const int* pc_dst = (const int*)d_in[4];
    const int* ps_src = (const int*)d_in[5];
    const int* ps_dst = (const int*)d_in[6];
    const float* W_proj = (const float*)d_in[7];
    const float* b_proj = (const float*)d_in[8];
    const float* emb_brand = (const float*)d_in[9];
    const float* emb_cat = (const float*)d_in[10];
    const float* emb_shop = (const float*)d_in[11];
    const float* W1_l = (const float*)d_in[12];
    const float* b1_l = (const float*)d_in[13];
    const float* W1_r = (const float*)d_in[14];
    const float* W2_l = (const float*)d_in[15];
    const float* b2_l = (const float*)d_in[16];
    const float* W2_r = (const float*)d_in[17];
    float* out = (float*)d_out;

    const int nodeBlocks = (NTOT + 255) / 256;
    const int edgeBlocks = (3 * NE + 255) / 256;
    const int aggBlocks = (NTOT * 32 + 255) / 256;

    // --- build CSR once (shared by both layers) ---
    zero_deg<<<nodeBlocks, 256>>>();
    hist_edges<<<edgeBlocks, 256>>>(pb_src, pb_dst, pc_src, pc_dst, ps_src, ps_dst);
    scanA<<<NBLK_SCAN, 256>>>();
    scanB<<<1, 512>>>();
    scanC<<<nodeBlocks, 256>>>();
    fill_csr<<<edgeBlocks, 256>>>(pb_src, pb_dst, pc_src, pc_dst, ps_src, ps_dst);

    // --- node feature assembly ---
    proj_kernel<<<(NP + 255) / 256, 256>>>(x_product, W_proj, b_proj);
    copy_emb<<<((NB + NC + NS) * H / 4 + 255) / 256, 256>>>(emb_brand, emb_cat, emb_shop);

    // --- layer 1 ---
    aggregate<<<aggBlocks, 256>>>(0);
    finalize_gemm<256, 64, 32, true, false><<<(NTOT + 255) / 256, 256>>>(W1_r, W1_l, b1_l, out);
    // --- layer 2 ---
    aggregate<<<aggBlocks, 256>>>(1);
    finalize_gemm<512, 32, 16, false, true><<<(NTOT + 511) / 512, 256>>>(W2_r, W2_l, b2_l, out);
}

// round 3
// speedup vs baseline: 1.9261x; 1.8376x over previous
#include <cuda_runtime.h>
#include <cstdint>

#define NP 500000
#define NB 20000
#define NC 5000
#define NS 2000
#define NTOT 527000
#define NE 500000
#define EDIR (3 * NE * 2)
#define H 64
#define FIN 384

#define SCAN_SPAN 2048
#define NBLK_SCAN ((NTOT + SCAN_SPAN - 1) / SCAN_SPAN)

// ---------------- scratch ----------------------------------------------------
__device__ float g_x[(size_t)NTOT * H];
__device__ float g_h[(size_t)NTOT * H];
__device__ float g_agg[(size_t)NTOT * H];
__device__ int   g_deg[NTOT];
__device__ int   g_rowstart[NTOT];
__device__ int   g_cursor[NTOT];
__device__ int   g_scaninc[NTOT];
__device__ int   g_blocksum[512];
__device__ int   g_adj[EDIR];

// ---------------- tf32 helpers ----------------------------------------------
__device__ __forceinline__ uint32_t f2tf(float x) {
    uint32_t r;
    asm("cvt.rna.tf32.f32 %0, %1;" : "=r"(r) : "f"(x));
    return r;
}
__device__ __forceinline__ void mma_tf32(float* d, uint32_t a0, uint32_t a1,
                                         uint32_t a2, uint32_t a3,
                                         uint32_t b0, uint32_t b1) {
    asm volatile(
        "mma.sync.aligned.m16n8k8.row.col.f32.tf32.tf32.f32 "
        "{%0,%1,%2,%3},{%4,%5,%6,%7},{%8,%9},{%0,%1,%2,%3};"
        : "+f"(d[0]), "+f"(d[1]), "+f"(d[2]), "+f"(d[3])
        : "r"(a0), "r"(a1), "r"(a2), "r"(a3), "r"(b0), "r"(b1));
}

// ---------------- CSR build ---------------------------------------------------
__global__ void __launch_bounds__(256) zero_deg() {
    int i = blockIdx.x * 256 + threadIdx.x;
    if (i < NTOT) g_deg[i] = 0;
}

__global__ void __launch_bounds__(256) hist_edges(
    const int* __restrict__ pb_src, const int* __restrict__ pb_dst,
    const int* __restrict__ pc_src, const int* __restrict__ pc_dst,
    const int* __restrict__ ps_src, const int* __restrict__ ps_dst) {
    int e = blockIdx.x * 256 + threadIdx.x;
    if (e >= 3 * NE) return;
    int t = e / NE, i = e - t * NE;
    const int* sp; const int* dp; int off;
    if (t == 0)      { sp = pb_src; dp = pb_dst; off = NP; }
    else if (t == 1) { sp = pc_src; dp = pc_dst; off = NP + NB; }
    else             { sp = ps_src; dp = ps_dst; off = NP + NB + NC; }
    int p = __ldg(sp + i);
    int o = __ldg(dp + i) + off;
    atomicAdd(&g_deg[p], 1);
    atomicAdd(&g_deg[o], 1);
}

__global__ void __launch_bounds__(256) scanA() {
    __shared__ int wsum[8];
    __shared__ int wpre[8];
    int tid = threadIdx.x, lane = tid & 31, wid = tid >> 5;
    int base = blockIdx.x * SCAN_SPAN + tid * 8;
    int v[8], run = 0;
#pragma unroll
    for (int t = 0; t < 8; t++) {
        int idx = base + t;
        int d = (idx < NTOT) ? g_deg[idx] : 0;
        run += d;
        v[t] = run;
    }
    int tot = run;
#pragma unroll
    for (int off = 1; off < 32; off <<= 1) {
        int n = __shfl_up_sync(0xffffffffu, tot, off);
        if (lane >= off) tot += n;
    }
    int wexcl = tot - run;
    if (lane == 31) wsum[wid] = tot;
    __syncthreads();
    if (tid < 8) {
        int s = wsum[tid];
        int r = s;
#pragma unroll
        for (int off = 1; off < 8; off <<= 1) {
            int n = __shfl_up_sync(0xffu, r, off);
            if (tid >= off) r += n;
        }
        wpre[tid] = r - s;
        if (tid == 7) g_blocksum[blockIdx.x] = r;
    }
    __syncthreads();
    int bexcl = wexcl + wpre[wid];
#pragma unroll
    for (int t = 0; t < 8; t++) {
        int idx = base + t;
        if (idx < NTOT) g_scaninc[idx] = v[t] + bexcl;
    }
}

__global__ void __launch_bounds__(512) scanB() {
    __shared__ int s[NBLK_SCAN];
    int tid = threadIdx.x;
    if (tid < NBLK_SCAN) s[tid] = g_blocksum[tid];
    __syncthreads();
    if (tid == 0) {
        int run = 0;
        for (int i = 0; i < NBLK_SCAN; i++) { int t = s[i]; s[i] = run; run += t; }
    }
    __syncthreads();
    if (tid < NBLK_SCAN) g_blocksum[tid] = s[tid];
}

__global__ void __launch_bounds__(256) scanC() {
    int i = blockIdx.x * 256 + threadIdx.x;
    if (i >= NTOT) return;
    int start = g_scaninc[i] + g_blocksum[i >> 11] - g_deg[i];
    g_rowstart[i] = start;
    g_cursor[i] = start;
}

__global__ void __launch_bounds__(256) fill_csr(
    const int* __restrict__ pb_src, const int* __restrict__ pb_dst,
    const int* __restrict__ pc_src, const int* __restrict__ pc_dst,
    const int* __restrict__ ps_src, const int* __restrict__ ps_dst) {
    int e = blockIdx.x * 256 + threadIdx.x;
    if (e >= 3 * NE) return;
    int t = e / NE, i = e - t * NE;
    const int* sp; const int* dp; int off;
    if (t == 0)      { sp = pb_src; dp = pb_dst; off = NP; }
    else if (t == 1) { sp = pc_src; dp = pc_dst; off = NP + NB; }
    else             { sp = ps_src; dp = ps_dst; off = NP + NB + NC; }
    int p = __ldg(sp + i);
    int o = __ldg(dp + i) + off;
    int pos = atomicAdd(&g_cursor[o], 1);
    g_adj[pos] = p;
    int pos2 = atomicAdd(&g_cursor[p], 1);
    g_adj[pos2] = o;
}

// ---------------- feature assembly --------------------------------------------
__global__ void __launch_bounds__(256) copy_emb(const float* __restrict__ eb,
                                                const float* __restrict__ ec,
                                                const float* __restrict__ es) {
    int i = blockIdx.x * 256 + threadIdx.x;
    const int tot = (NB + NC + NS) * H / 4;
    if (i >= tot) return;
    const int nb4 = NB * H / 4, nc4 = NC * H / 4;
    float4 v;
    if (i < nb4) v = reinterpret_cast<const float4*>(eb)[i];
    else if (i < nb4 + nc4) v = reinterpret_cast<const float4*>(ec)[i - nb4];
    else v = reinterpret_cast<const float4*>(es)[i - nb4 - nc4];
    reinterpret_cast<float4*>(g_x)[(size_t)NP * H / 4 + i] = v;
}

// ---------------- proj: relu(x_product @ W_proj^T + b) via tf32 HMMA ----------
// Block: 256 thr (8 warps), tile M=128 x N=64, K-chunks of 16.
__global__ void __launch_bounds__(256) proj_tc(const float* __restrict__ A,
                                               const float* __restrict__ W,
                                               const float* __restrict__ bias) {
    __shared__ uint32_t As[128][20];
    __shared__ uint32_t Ws[64][20];
    const int tid = threadIdx.x;
    const int m0 = blockIdx.x * 128;
    const int warp = tid >> 5, lane = tid & 31;
    const int g = lane >> 2, t = lane & 3;

    float acc[8][4];
#pragma unroll
    for (int j = 0; j < 8; j++)
#pragma unroll
        for (int c = 0; c < 4; c++) acc[j][c] = 0.f;

    for (int kb = 0; kb < FIN; kb += 16) {
#pragma unroll
        for (int q = 0; q < 2; q++) {
            int idx = tid + 256 * q;
            int row = idx >> 2, c4 = idx & 3;
            int rg = m0 + row; if (rg > NP - 1) rg = NP - 1;
            float4 v = *reinterpret_cast<const float4*>(A + (size_t)rg * FIN + kb + c4 * 4);
            uint4 u = make_uint4(f2tf(v.x), f2tf(v.y), f2tf(v.z), f2tf(v.w));
            *reinterpret_cast<uint4*>(&As[row][c4 * 4]) = u;
        }
        {
            int n = tid >> 2, c4 = tid & 3;
            float4 v = *reinterpret_cast<const float4*>(W + (size_t)n * FIN + kb + c4 * 4);
            uint4 u = make_uint4(f2tf(v.x), f2tf(v.y), f2tf(v.z), f2tf(v.w));
            *reinterpret_cast<uint4*>(&Ws[n][c4 * 4]) = u;
        }
        __syncthreads();
        const int r0 = warp * 16;
#pragma unroll
        for (int ks = 0; ks < 2; ks++) {
            int k0 = ks * 8;
            uint32_t a0 = As[r0 + g][k0 + t];
            uint32_t a1 = As[r0 + g + 8][k0 + t];
            uint32_t a2 = As[r0 + g][k0 + t + 4];
            uint32_t a3 = As[r0 + g + 8][k0 + t + 4];
#pragma unroll
            for (int j = 0; j < 8; j++) {
                uint32_t b0 = Ws[j * 8 + g][k0 + t];
                uint32_t b1 = Ws[j * 8 + g][k0 + t + 4];
                mma_tf32(acc[j], a0, a1, a2, a3, b0, b1);
            }
        }
        __syncthreads();
    }
#pragma unroll
    for (int j = 0; j < 8; j++) {
        int col = j * 8 + 2 * t;
        float b0 = bias[col], b1 = bias[col + 1];
        int r1 = m0 + warp * 16 + g;
        if (r1 < NP) {
            float2 o = make_float2(fmaxf(acc[j][0] + b0, 0.f), fmaxf(acc[j][1] + b1, 0.f));
            *reinterpret_cast<float2*>(g_x + (size_t)r1 * H + col) = o;
        }
        int r2 = r1 + 8;
        if (r2 < NP) {
            float2 o = make_float2(fmaxf(acc[j][2] + b0, 0.f), fmaxf(acc[j][3] + b1, 0.f));
            *reinterpret_cast<float2*>(g_x + (size_t)r2 * H + col) = o;
        }
    }
}

// ---------------- CSR mean aggregation: one warp per node ---------------------
__global__ void __launch_bounds__(256) aggregate(int use_h) {
    int gw = (blockIdx.x * 256 + threadIdx.x) >> 5;
    if (gw >= NTOT) return;
    int lane = threadIdx.x & 31;
    int start = g_rowstart[gw];
    int deg = g_deg[gw];
    const float* __restrict__ x = use_h ? g_h : g_x;
    int half = lane >> 4;
    int f = (lane & 15) * 4;
    float4 acc = make_float4(0.f, 0.f, 0.f, 0.f);
    for (int it = 0; 2 * it + half < deg; it++) {
        int s = __ldg(g_adj + start + 2 * it + half);
        float4 v = *reinterpret_cast<const float4*>(x + (size_t)s * H + f);
        acc.x += v.x; acc.y += v.y; acc.z += v.z; acc.w += v.w;
    }
    acc.x += __shfl_xor_sync(0xffffffffu, acc.x, 16);
    acc.y += __shfl_xor_sync(0xffffffffu, acc.y, 16);
    acc.z += __shfl_xor_sync(0xffffffffu, acc.z, 16);
    acc.w += __shfl_xor_sync(0xffffffffu, acc.w, 16);
    if (lane < 16) {
        float inv = 1.f / fmaxf((float)deg, 1.f);
        float4 o = make_float4(acc.x * inv, acc.y * inv, acc.z * inv, acc.w * inv);
        *reinterpret_cast<float4*>(g_agg + (size_t)gw * H + f) = o;
    }
}

// ---------------- SAGE finalize via tf32 HMMA ---------------------------------
// C = x @ Wr^T + mean @ Wl^T + b. Virtual K=128 (k<64: x/Wr, k>=64: agg/Wl).
template <int NOUT, bool RELU, bool USEH>
__global__ void __launch_bounds__(256) finalize_tc(const float* __restrict__ Wr,
                                                   const float* __restrict__ Wl,
                                                   const float* __restrict__ bias,
                                                   float* __restrict__ outp) {
    constexpr int NT = NOUT / 8;
    __shared__ uint32_t As[128][20];
    __shared__ uint32_t Ws[NOUT][20];
    const int tid = threadIdx.x;
    const int m0 = blockIdx.x * 128;
    const int warp = tid >> 5, lane = tid & 31;
    const int g = lane >> 2, t = lane & 3;
    const float* xsrc = USEH ? g_h : g_x;
    float* out = (NOUT == H) ? g_h : outp;

    float acc[NT][4];
#pragma unroll
    for (int j = 0; j < NT; j++)
#pragma unroll
        for (int c = 0; c < 4; c++) acc[j][c] = 0.f;

    for (int kb = 0; kb < 2 * H; kb += 16) {
        const float* src = (kb < H) ? xsrc : g_agg;
        const float* W = (kb < H) ? Wr : Wl;
        const int kcol = kb & (H - 1);
#pragma unroll
        for (int q = 0; q < 2; q++) {
            int idx = tid + 256 * q;
            int row = idx >> 2, c4 = idx & 3;
            int rg = m0 + row; if (rg > NTOT - 1) rg = NTOT - 1;
            float4 v = *reinterpret_cast<const float4*>(src + (size_t)rg * H + kcol + c4 * 4);
            uint4 u = make_uint4(f2tf(v.x), f2tf(v.y), f2tf(v.z), f2tf(v.w));
            *reinterpret_cast<uint4*>(&As[row][c4 * 4]) = u;
        }
        if (tid < NOUT * 4) {
            int n = tid >> 2, c4 = tid & 3;
            float4 v = *reinterpret_cast<const float4*>(W + (size_t)n * H + kcol + c4 * 4);
            uint4 u = make_uint4(f2tf(v.x), f2tf(v.y), f2tf(v.z), f2tf(v.w));
            *reinterpret_cast<uint4*>(&Ws[n][c4 * 4]) = u;
        }
        __syncthreads();
        const int r0 = warp * 16;
#pragma unroll
        for (int ks = 0; ks < 2; ks++) {
            int k0 = ks * 8;
            uint32_t a0 = As[r0 + g][k0 + t];
            uint32_t a1 = As[r0 + g + 8][k0 + t];
            uint32_t a2 = As[r0 + g][k0 + t + 4];
            uint32_t a3 = As[r0 + g + 8][k0 + t + 4];
#pragma unroll
            for (int j = 0; j < NT; j++) {
                uint32_t b0 = Ws[j * 8 + g][k0 + t];
                uint32_t b1 = Ws[j * 8 + g][k0 + t + 4];
                mma_tf32(acc[j], a0, a1, a2, a3, b0, b1);
            }
        }
        __syncthreads();
    }
#pragma unroll
    for (int j = 0; j < NT; j++) {
        int col = j * 8 + 2 * t;
        float b0 = bias[col], b1 = bias[col + 1];
        int r1 = m0 + warp * 16 + g;
        if (r1 < NTOT) {
            float v0 = acc[j][0] + b0, v1 = acc[j][1] + b1;
            if (RELU) { v0 = fmaxf(v0, 0.f); v1 = fmaxf(v1, 0.f); }
            *reinterpret_cast<float2*>(out + (size_t)r1 * NOUT + col) = make_float2(v0, v1);
        }
        int r2 = r1 + 8;
        if (r2 < NTOT) {
            float v2 = acc[j][2] + b0, v3 = acc[j][3] + b1;
            if (RELU) { v2 = fmaxf(v2, 0.f); v3 = fmaxf(v3, 0.f); }
            *reinterpret_cast<float2*>(out + (size_t)r2 * NOUT + col) = make_float2(v2, v3);
        }
    }
}

// ---------------- launch -------------------------------------------------------
extern "C" void kernel_launch(void* const* d_in, const int* in_sizes, int n_in,
                              void* d_out, int out_size) {
    const float* x_product = (const float*)d_in[0];
    const int* pb_src = (const int*)d_in[1];
    const int* pb_dst = (const int*)d_in[2];
    const int* pc_src = (const int*)d_in[3];
    const int* pc_dst = (const int*)d_in[4];
    const int* ps_src = (const int*)d_in[5];
    const int* ps_dst = (const int*)d_in[6];
    const float* W_proj = (const float*)d_in[7];
    const float* b_proj = (const float*)d_in[8];
    const float* emb_brand = (const float*)d_in[9];
    const float* emb_cat = (const float*)d_in[10];
    const float* emb_shop = (const float*)d_in[11];
    const float* W1_l = (const float*)d_in[12];
    const float* b1_l = (const float*)d_in[13];
    const float* W1_r = (const float*)d_in[14];
    const float* W2_l = (const float*)d_in[15];
    const float* b2_l = (const float*)d_in[16];
    const float* W2_r = (const float*)d_in[17];
    float* out = (float*)d_out;

    const int nodeBlocks = (NTOT + 255) / 256;
    const int edgeBlocks = (3 * NE + 255) / 256;
    const int aggBlocks = (NTOT * 32 + 255) / 256;
    const int gemmBlocks = (NTOT + 127) / 128;

    // --- build CSR once ---
    zero_deg<<<nodeBlocks, 256>>>();
    hist_edges<<<edgeBlocks, 256>>>(pb_src, pb_dst, pc_src, pc_dst, ps_src, ps_dst);
    scanA<<<NBLK_SCAN, 256>>>();
    scanB<<<1, 512>>>();
    scanC<<<nodeBlocks, 256>>>();
    fill_csr<<<edgeBlocks, 256>>>(pb_src, pb_dst, pc_src, pc_dst, ps_src, ps_dst);

    // --- node feature assembly ---
    proj_tc<<<(NP + 127) / 128, 256>>>(x_product, W_proj, b_proj);
    copy_emb<<<((NB + NC + NS) * H / 4 + 255) / 256, 256>>>(emb_brand, emb_cat, emb_shop);

    // --- layer 1 ---
    aggregate<<<aggBlocks, 256>>>(0);
    finalize_tc<64, true, false><<<gemmBlocks, 256>>>(W1_r, W1_l, b1_l, out);
    // --- layer 2 ---
    aggregate<<<aggBlocks, 256>>>(1);
    finalize_tc<32, false, true><<<gemmBlocks, 256>>>(W2_r, W2_l, b2_l, out);
}